// round 9
// baseline (speedup 1.0000x reference)
#include <cuda_runtime.h>
#include <cuda_fp16.h>
#include <cuda_bf16.h>

#define HINGES 1024

// out(x) = P + S*(x - c*delta), c = ceil(x/delta), t = clamp(c+511, 0, 1023).
// (P,S) built in fp32 replicating reference clamp+wrap gather semantics,
// stored fp16 (P anchored at x0 = c*delta so fp16 error is output-relative).
// Tails via exact fp32 selects.
__device__ __forceinline__ float adact1(float xv, const __half2* __restrict__ tabh,
                                        float r, float s, float delta, float inv_delta,
                                        float a0, float aL) {
    float q  = __fmul_rn(xv, inv_delta);
    float cf = ceilf(q);
    int   c  = (int)cf;
    int   t  = min(max(c + 511, 0), HINGES - 1);
    float2 ps = __half22float2(tabh[t]);     // one LDS.32
    float xa = __fmaf_rn(-delta, cf, xv);    // x - c*delta
    float v  = __fmaf_rn(ps.y, xa, ps.x);
    v = (xv < r) ? a0 : v;
    v = (xv > s) ? aL : v;
    return v;
}

__global__ __launch_bounds__(256, 8)
void adact_kernel(const float4* __restrict__ x,
                  const float*  __restrict__ ns,
                  const float*  __restrict__ a,
                  float4* __restrict__ out, int n4, int chunk) {
    __shared__ __half2 tabh[HINGES];         // 4 KB (P,S) per bin

    const float r     = ns[0];
    const float s     = ns[HINGES - 1];
    const float a0    = a[0];
    const float aL    = a[HINGES - 1];
    const float delta = __fadd_rn(ns[1], -ns[0]);
    const float inv_delta = __fdiv_rn(1.0f, delta);

    // Build anchored-affine table (reference clamp+wrap logic, fp32).
    #pragma unroll
    for (int t = threadIdx.x; t < HINGES; t += 256) {
        int c  = t - 511;
        int m1 = max(c - 1, 0);
        m1 = min(m1, HINGES - 1);
        int m2 = c;
        if (m2 >= HINGES) m2 = HINGES - 1;
        if (m2 < 0)       m2 += HINGES;
        m2 = min(max(m2, 0), HINGES - 1);

        float ns1 = ns[m1], ns2 = ns[m2];
        float a1  = a[m1],  a2  = a[m2];
        float denom = __fadd_rn(ns2, -ns1);
        denom = (denom == 0.0f) ? 1.0f : denom;

        float x0 = __fmul_rn((float)c, delta);
        float w1 = __fdiv_rn(__fadd_rn(ns2, -x0), denom);
        float w2 = __fdiv_rn(__fadd_rn(x0, -ns1), denom);
        float P  = __fadd_rn(__fmul_rn(w1, a1), __fmul_rn(w2, a2));
        float S  = __fdiv_rn(__fadd_rn(a2, -a1), denom);
        tabh[t] = __floats2half2_rn(P, S);
    }
    __syncthreads();

    // Contiguous per-CTA chunk: each iteration streams one 16 KB sequential
    // run (4 x 4 KB front-batched LDG.128 waves), advancing linearly through
    // the chunk for DRAM row-buffer locality. Same 32-reg / 64-warp/SM config
    // as the 51.5us kernel.
    const int begin = blockIdx.x * chunk;
    const int end   = min(begin + chunk, n4);
    int idx = begin + threadIdx.x;

    for (; idx + 768 < end; idx += 1024) {
        float4 v0 = __ldcs(&x[idx]);
        float4 v1 = __ldcs(&x[idx + 256]);
        float4 v2 = __ldcs(&x[idx + 512]);
        float4 v3 = __ldcs(&x[idx + 768]);

        float4 o0, o1, o2, o3;
        o0.x = adact1(v0.x, tabh, r, s, delta, inv_delta, a0, aL);
        o0.y = adact1(v0.y, tabh, r, s, delta, inv_delta, a0, aL);
        o0.z = adact1(v0.z, tabh, r, s, delta, inv_delta, a0, aL);
        o0.w = adact1(v0.w, tabh, r, s, delta, inv_delta, a0, aL);
        o1.x = adact1(v1.x, tabh, r, s, delta, inv_delta, a0, aL);
        o1.y = adact1(v1.y, tabh, r, s, delta, inv_delta, a0, aL);
        o1.z = adact1(v1.z, tabh, r, s, delta, inv_delta, a0, aL);
        o1.w = adact1(v1.w, tabh, r, s, delta, inv_delta, a0, aL);
        o2.x = adact1(v2.x, tabh, r, s, delta, inv_delta, a0, aL);
        o2.y = adact1(v2.y, tabh, r, s, delta, inv_delta, a0, aL);
        o2.z = adact1(v2.z, tabh, r, s, delta, inv_delta, a0, aL);
        o2.w = adact1(v2.w, tabh, r, s, delta, inv_delta, a0, aL);
        o3.x = adact1(v3.x, tabh, r, s, delta, inv_delta, a0, aL);
        o3.y = adact1(v3.y, tabh, r, s, delta, inv_delta, a0, aL);
        o3.z = adact1(v3.z, tabh, r, s, delta, inv_delta, a0, aL);
        o3.w = adact1(v3.w, tabh, r, s, delta, inv_delta, a0, aL);

        __stcs(&out[idx],       o0);
        __stcs(&out[idx + 256], o1);
        __stcs(&out[idx + 512], o2);
        __stcs(&out[idx + 768], o3);
    }
    for (; idx < end; idx += 256) {
        float4 v = __ldcs(&x[idx]);
        float4 o;
        o.x = adact1(v.x, tabh, r, s, delta, inv_delta, a0, aL);
        o.y = adact1(v.y, tabh, r, s, delta, inv_delta, a0, aL);
        o.z = adact1(v.z, tabh, r, s, delta, inv_delta, a0, aL);
        o.w = adact1(v.w, tabh, r, s, delta, inv_delta, a0, aL);
        __stcs(&out[idx], o);
    }
}

extern "C" void kernel_launch(void* const* d_in, const int* in_sizes, int n_in,
                              void* d_out, int out_size) {
    const float* x  = (const float*)d_in[0];
    const float* ns = (const float*)d_in[1];
    const float* a  = (const float*)d_in[2];
    float* out = (float*)d_out;

    int n  = in_sizes[0];
    int n4 = n >> 2;

    const int blocks = 148 * 8;              // persistent, one wave
    int chunk = (n4 + blocks - 1) / blocks;  // contiguous slice per CTA

    adact_kernel<<<blocks, 256>>>((const float4*)x, ns, a, (float4*)out, n4, chunk);
}